// round 1
// baseline (speedup 1.0000x reference)
#include <cuda_runtime.h>
#include <cstdint>

#define K_DIM 4096
#define N_DIM 4096
#define NG    512          // groups per input row
#define M_MAX 8192

#define BM 128
#define BN 128
#define BK 16
#define NTHREADS 128
#define ASTRIDE (BK + 4)   // 20 floats -> conflict-free frag loads (20 mod 32 pattern)
#define BSTRIDE (BN + 4)   // 132 floats -> 4 mod 32 pattern, conflict-free

// Scratch (static __device__ arrays: allowed; no runtime allocation)
__device__ float g_W[(size_t)K_DIM * N_DIM];   // dequantized W_T, tf32-rounded [K,N]
__device__ float g_X[(size_t)M_MAX * K_DIM];   // tf32-rounded copy of x
__device__ int   g_lab64;                      // 1 if labels are int64, 0 if int32

__device__ __forceinline__ float to_tf32(float x) {
    uint32_t u;
    asm("cvt.rna.tf32.f32 %0, %1;" : "=r"(u) : "f"(x));
    return __uint_as_float(u);
}

// ---------------------------------------------------------------------------
// Label dtype detection: int64 little-endian => every odd int32 word is the
// high half of a value < 65536, i.e. exactly 0. With int32 labels those words
// are random labels (P(all 64 == 0) ~ 65536^-64).
// ---------------------------------------------------------------------------
__global__ void detect_labels_kernel(const int* __restrict__ labels32) {
    if (threadIdx.x == 0 && blockIdx.x == 0) {
        int all_zero = 1;
        for (int i = 0; i < 64; i++) {
            if (labels32[2 * i + 1] != 0) { all_zero = 0; break; }
        }
        g_lab64 = all_zero;
    }
}

// ---------------------------------------------------------------------------
// Dequant: W_T[i, g*8+j] = centroids[labels[i,g], j] / max(scale[i],1e-8),
// rna-rounded to tf32. idx = i*512 + g; output offset = idx*8.
// ---------------------------------------------------------------------------
__global__ void dequant_kernel(const float* __restrict__ centroids,
                               const void* __restrict__ labels_raw,
                               const float* __restrict__ scale) {
    int idx = blockIdx.x * blockDim.x + threadIdx.x;
    if (idx >= K_DIM * NG) return;
    int i = idx >> 9;

    long long lab;
    if (g_lab64) lab = ((const long long*)labels_raw)[idx];
    else         lab = (long long)((const int*)labels_raw)[idx];

    float rs = 1.0f / fmaxf(__ldg(scale + i), 1e-8f);
    const float4* c = reinterpret_cast<const float4*>(centroids + (size_t)lab * 8);
    float4 v0 = __ldg(c);
    float4 v1 = __ldg(c + 1);
    v0.x = to_tf32(v0.x * rs); v0.y = to_tf32(v0.y * rs);
    v0.z = to_tf32(v0.z * rs); v0.w = to_tf32(v0.w * rs);
    v1.x = to_tf32(v1.x * rs); v1.y = to_tf32(v1.y * rs);
    v1.z = to_tf32(v1.z * rs); v1.w = to_tf32(v1.w * rs);
    float4* dst = reinterpret_cast<float4*>(g_W + (size_t)idx * 8);
    dst[0] = v0;
    dst[1] = v1;
}

// ---------------------------------------------------------------------------
// rna-round x to tf32 (so the MMA sees round-to-nearest, not truncation)
// ---------------------------------------------------------------------------
__global__ void round_x_kernel(const float* __restrict__ x, int n4) {
    int idx = blockIdx.x * blockDim.x + threadIdx.x;
    if (idx >= n4) return;
    float4 v = __ldg(reinterpret_cast<const float4*>(x) + idx);
    v.x = to_tf32(v.x); v.y = to_tf32(v.y);
    v.z = to_tf32(v.z); v.w = to_tf32(v.w);
    reinterpret_cast<float4*>(g_X)[idx] = v;
}

// ---------------------------------------------------------------------------
// GEMM: out[M,N] = g_X[M,K] @ g_W[K,N] + bias, tf32 mma.sync, fp32 accum.
// 128x128 block, BK=16, 4 warps each computing 64x64 (4 m-tiles x 8 n-tiles
// of m16n8k8). cp.async double-buffered smem pipeline.
// ---------------------------------------------------------------------------
__device__ __forceinline__ void cp16(uint32_t saddr, const float* g) {
    asm volatile("cp.async.cg.shared.global [%0], [%1], 16;" :: "r"(saddr), "l"(g));
}

__global__ void __launch_bounds__(NTHREADS, 2)
gemm_kernel(const float* __restrict__ bias, float* __restrict__ out) {
    __shared__ float As[2][BM][ASTRIDE];   // 20480 B
    __shared__ float Bs[2][BK][BSTRIDE];   // 16896 B

    const int tid  = threadIdx.x;
    const int lane = tid & 31;
    const int wid  = tid >> 5;
    const int bm = blockIdx.y * BM;
    const int bn = blockIdx.x * BN;
    const int wm = (wid >> 1) * 64;
    const int wn = (wid & 1) * 64;

    // gmem staging mapping (float4 granularity)
    const int arow = tid >> 2;          // 0..31 (+i*32)
    const int acol = (tid & 3) * 4;     // 0,4,8,12
    const int brow = tid >> 5;          // 0..3 (+i*4)
    const int bcol = (tid & 31) * 4;    // 0..124
    const float* aptr = g_X + (size_t)(bm + arow) * K_DIM + acol;
    const float* bptr = g_W + (size_t)brow * N_DIM + bn + bcol;

    uint32_t sA[2], sB[2];
    #pragma unroll
    for (int b = 0; b < 2; b++) {
        sA[b] = (uint32_t)__cvta_generic_to_shared(&As[b][arow][acol]);
        sB[b] = (uint32_t)__cvta_generic_to_shared(&Bs[b][brow][bcol]);
    }

    float c[4][8][4];
    #pragma unroll
    for (int mi = 0; mi < 4; mi++)
        #pragma unroll
        for (int ni = 0; ni < 8; ni++) {
            c[mi][ni][0] = 0.f; c[mi][ni][1] = 0.f;
            c[mi][ni][2] = 0.f; c[mi][ni][3] = 0.f;
        }

    const int KT = K_DIM / BK;   // 256

    // prologue: prefetch tile 0 -> buf 0
    #pragma unroll
    for (int i = 0; i < 4; i++) {
        cp16(sA[0] + i * 32 * ASTRIDE * 4, aptr + (size_t)i * 32 * K_DIM);
        cp16(sB[0] + i * 4 * BSTRIDE * 4,  bptr + (size_t)i * 4 * N_DIM);
    }
    asm volatile("cp.async.commit_group;");

    for (int t = 0; t < KT; t++) {
        const int buf = t & 1;
        if (t + 1 < KT) {
            const int nb = (t + 1) & 1;
            const float* ap = aptr + (size_t)(t + 1) * BK;
            const float* bp = bptr + (size_t)(t + 1) * BK * N_DIM;
            #pragma unroll
            for (int i = 0; i < 4; i++) {
                cp16(sA[nb] + i * 32 * ASTRIDE * 4, ap + (size_t)i * 32 * K_DIM);
                cp16(sB[nb] + i * 4 * BSTRIDE * 4,  bp + (size_t)i * 4 * N_DIM);
            }
            asm volatile("cp.async.commit_group;");
            asm volatile("cp.async.wait_group 1;");
        } else {
            asm volatile("cp.async.wait_group 0;");
        }
        __syncthreads();

        #pragma unroll
        for (int kk = 0; kk < BK; kk += 8) {
            uint32_t a[4][4], b[8][2];
            const int kc = kk + (lane & 3);
            #pragma unroll
            for (int mi = 0; mi < 4; mi++) {
                const int r = wm + mi * 16 + (lane >> 2);
                a[mi][0] = __float_as_uint(As[buf][r][kc]);
                a[mi][1] = __float_as_uint(As[buf][r + 8][kc]);
                a[mi][2] = __float_as_uint(As[buf][r][kc + 4]);
                a[mi][3] = __float_as_uint(As[buf][r + 8][kc + 4]);
            }
            #pragma unroll
            for (int ni = 0; ni < 8; ni++) {
                const int cn = wn + ni * 8 + (lane >> 2);
                b[ni][0] = __float_as_uint(Bs[buf][kc][cn]);
                b[ni][1] = __float_as_uint(Bs[buf][kc + 4][cn]);
            }
            #pragma unroll
            for (int mi = 0; mi < 4; mi++)
                #pragma unroll
                for (int ni = 0; ni < 8; ni++)
                    asm volatile(
                        "mma.sync.aligned.m16n8k8.row.col.f32.tf32.tf32.f32 "
                        "{%0,%1,%2,%3}, {%4,%5,%6,%7}, {%8,%9}, {%0,%1,%2,%3};"
                        : "+f"(c[mi][ni][0]), "+f"(c[mi][ni][1]),
                          "+f"(c[mi][ni][2]), "+f"(c[mi][ni][3])
                        : "r"(a[mi][0]), "r"(a[mi][1]), "r"(a[mi][2]), "r"(a[mi][3]),
                          "r"(b[ni][0]), "r"(b[ni][1]));
        }
        __syncthreads();
    }

    // epilogue: bias add + fp32 store (float2 per fragment row-pair)
    #pragma unroll
    for (int mi = 0; mi < 4; mi++) {
        const int row = bm + wm + mi * 16 + (lane >> 2);
        #pragma unroll
        for (int ni = 0; ni < 8; ni++) {
            const int col = bn + wn + ni * 8 + 2 * (lane & 3);
            const float2 bv = *reinterpret_cast<const float2*>(bias + col);
            float2 r0 = make_float2(c[mi][ni][0] + bv.x, c[mi][ni][1] + bv.y);
            float2 r1 = make_float2(c[mi][ni][2] + bv.x, c[mi][ni][3] + bv.y);
            *reinterpret_cast<float2*>(out + (size_t)row * N_DIM + col) = r0;
            *reinterpret_cast<float2*>(out + (size_t)(row + 8) * N_DIM + col) = r1;
        }
    }
}

// ---------------------------------------------------------------------------
extern "C" void kernel_launch(void* const* d_in, const int* in_sizes, int n_in,
                              void* d_out, int out_size) {
    const float* x         = (const float*)d_in[0];
    const float* centroids = (const float*)d_in[1];
    const void*  labels    = d_in[2];               // int64 or int32 (detected)
    const float* scale     = (const float*)d_in[3];
    const float* bias      = (const float*)d_in[4];
    float* out = (float*)d_out;

    const int M = in_sizes[0] / K_DIM;              // 8192

    detect_labels_kernel<<<1, 32>>>((const int*)labels);
    dequant_kernel<<<(K_DIM * NG + 255) / 256, 256>>>(centroids, labels, scale);
    const int n4 = (M * K_DIM) / 4;
    round_x_kernel<<<(n4 + 255) / 256, 256>>>(x, n4);
    gemm_kernel<<<dim3(N_DIM / BN, M / BM), NTHREADS>>>(bias, out);
}

// round 3
// speedup vs baseline: 1.3320x; 1.3320x over previous
#include <cuda_runtime.h>
#include <cstdint>

#define K_DIM 4096
#define N_DIM 4096
#define NG    512
#define M_MAX 8192

// ---- GEMM tiling ----
#define BM 128
#define BN 128
#define BK 32                   // 128 B per row -> full SW128 swizzle domain
#define NSTAGES 3
#define NTHREADS 256
#define STAGE_A 16384           // 128 rows x 128 B
#define STAGE_B 16384
#define STAGE_BYTES (STAGE_A + STAGE_B)

// Scratch (static __device__: allowed)
__device__ float g_X[(size_t)M_MAX * K_DIM];   // rna-tf32 rounded x  [M,K]
__device__ float g_B[(size_t)N_DIM * K_DIM];   // dequant W, K-major  [N,K]
__device__ int   g_lab64;

// ---------------- helpers ----------------
__device__ __forceinline__ float to_tf32(float x) {
    uint32_t u;
    asm("cvt.rna.tf32.f32 %0, %1;" : "=r"(u) : "f"(x));
    return __uint_as_float(u);
}
__device__ __forceinline__ uint32_t smem_u32(const void* p) {
    uint32_t a;
    asm("{ .reg .u64 t; cvta.to.shared.u64 t, %1; cvt.u32.u64 %0, t; }" : "=r"(a) : "l"(p));
    return a;
}
__device__ __forceinline__ void cp16(uint32_t saddr, const float* g) {
    asm volatile("cp.async.cg.shared.global [%0], [%1], 16;" :: "r"(saddr), "l"(g));
}
__device__ __forceinline__ void ldsm4(uint32_t& r0, uint32_t& r1, uint32_t& r2, uint32_t& r3,
                                      uint32_t addr) {
    asm volatile("ldmatrix.sync.aligned.m8n8.x4.shared.b16 {%0,%1,%2,%3}, [%4];"
                 : "=r"(r0), "=r"(r1), "=r"(r2), "=r"(r3) : "r"(addr));
}

// ---------------------------------------------------------------------------
// label dtype detection (jax may deliver int32 or int64)
// ---------------------------------------------------------------------------
__global__ void detect_labels_kernel(const int* __restrict__ labels32) {
    if (threadIdx.x == 0) {
        int all_zero = 1;
        for (int i = 0; i < 64; i++)
            if (labels32[2 * i + 1] != 0) { all_zero = 0; break; }
        g_lab64 = all_zero;
    }
}

// ---------------------------------------------------------------------------
// dequant + transpose: g_B[n][k] = tf32(centroids[labels[k, n/8]][n%8] / max(scale[k],1e-8))
// ---------------------------------------------------------------------------
__global__ void __launch_bounds__(256) dequant_kernel(const float* __restrict__ centroids,
                                                      const void* __restrict__ labels_raw,
                                                      const float* __restrict__ scale) {
    __shared__ float tile[128][65];
    const int tid = threadIdx.x;
    const int k0 = blockIdx.x * 64;
    const int n0 = blockIdx.y * 128;
    const int g0 = n0 >> 3;
    const bool l64 = (g_lab64 != 0);

    #pragma unroll
    for (int it = 0; it < 4; it++) {
        int id = it * 256 + tid;          // 1024 items: 64 k x 16 groups
        int kl = id >> 4, g = id & 15;
        int k = k0 + kl;
        long long lab = l64 ? ((const long long*)labels_raw)[(size_t)k * NG + g0 + g]
                            : (long long)((const int*)labels_raw)[(size_t)k * NG + g0 + g];
        float rs = 1.0f / fmaxf(__ldg(scale + k), 1e-8f);
        const float4* c = reinterpret_cast<const float4*>(centroids + (size_t)lab * 8);
        float4 v0 = __ldg(c), v1 = __ldg(c + 1);
        int nb = g * 8;
        tile[nb + 0][kl] = to_tf32(v0.x * rs); tile[nb + 1][kl] = to_tf32(v0.y * rs);
        tile[nb + 2][kl] = to_tf32(v0.z * rs); tile[nb + 3][kl] = to_tf32(v0.w * rs);
        tile[nb + 4][kl] = to_tf32(v1.x * rs); tile[nb + 5][kl] = to_tf32(v1.y * rs);
        tile[nb + 6][kl] = to_tf32(v1.z * rs); tile[nb + 7][kl] = to_tf32(v1.w * rs);
    }
    __syncthreads();
    #pragma unroll
    for (int it = 0; it < 8; it++) {
        int id = it * 256 + tid;          // 2048 items: 128 n x 16 k-float4
        int nl = id >> 4, k4 = (id & 15) * 4;
        float4 v = make_float4(tile[nl][k4], tile[nl][k4 + 1], tile[nl][k4 + 2], tile[nl][k4 + 3]);
        *reinterpret_cast<float4*>(g_B + (size_t)(n0 + nl) * K_DIM + k0 + k4) = v;
    }
}

// ---------------------------------------------------------------------------
// rna-round x to tf32
// ---------------------------------------------------------------------------
__global__ void round_x_kernel(const float* __restrict__ x, int n4) {
    int idx = blockIdx.x * blockDim.x + threadIdx.x;
    if (idx >= n4) return;
    float4 v = __ldg(reinterpret_cast<const float4*>(x) + idx);
    v.x = to_tf32(v.x); v.y = to_tf32(v.y);
    v.z = to_tf32(v.z); v.w = to_tf32(v.w);
    reinterpret_cast<float4*>(g_X)[idx] = v;
}

// ---------------------------------------------------------------------------
// GEMM: out = g_X @ g_B^T + bias.  128x128 CTA tile, 8 warps of 32x64,
// BK=32, 3-stage cp.async, SW128 swizzled smem, ldmatrix fragment loads,
// m16n8k8 tf32 mma.sync with fp32 accumulate.
// ---------------------------------------------------------------------------
__global__ void __launch_bounds__(NTHREADS, 2)
gemm_kernel(const float* __restrict__ bias, float* __restrict__ out) {
    extern __shared__ char smem_raw[];
    const uint32_t sb = smem_u32(smem_raw);

    const int tid  = threadIdx.x;
    const int wid  = tid >> 5;
    const int lane = tid & 31;
    const int bm = blockIdx.y * BM;
    const int bn = blockIdx.x * BN;
    const int wm = (wid & 3) * 32;        // warp tile 32 (m) x 64 (n)
    const int wn = (wid >> 2) * 64;

    // gmem staging mapping: 1024 16B chunks per operand, 4 per thread
    const int r0_ = tid >> 3;             // base row, +32 per iter? no: id = i*256+tid
    (void)r0_;

    float c[2][8][4];
    #pragma unroll
    for (int mi = 0; mi < 2; mi++)
        #pragma unroll
        for (int ni = 0; ni < 8; ni++) {
            c[mi][ni][0] = 0.f; c[mi][ni][1] = 0.f;
            c[mi][ni][2] = 0.f; c[mi][ni][3] = 0.f;
        }

    const int KT = K_DIM / BK;            // 128

    const float* gA0 = g_X + (size_t)bm * K_DIM;
    const float* gB0 = g_B + (size_t)bn * K_DIM;

    auto load_stage = [&](int slot, int t) {
        const uint32_t sa  = sb + slot * STAGE_BYTES;
        const uint32_t sbs = sa + STAGE_A;
        const float* gA = gA0 + t * BK;
        const float* gB = gB0 + t * BK;
        #pragma unroll
        for (int i = 0; i < 4; i++) {
            int id = i * 256 + tid;
            int r = id >> 3, cc = id & 7;
            cp16(sa + r * 128 + ((cc ^ (r & 7)) << 4), gA + (size_t)r * K_DIM + cc * 4);
        }
        #pragma unroll
        for (int i = 0; i < 4; i++) {
            int id = i * 256 + tid;
            int r = id >> 3, cc = id & 7;
            cp16(sbs + r * 128 + ((cc ^ (r & 7)) << 4), gB + (size_t)r * K_DIM + cc * 4);
        }
        asm volatile("cp.async.commit_group;");
    };

    load_stage(0, 0);
    load_stage(1, 1);

    // ldmatrix lane addressing (constant per thread up to chunk/kk)
    const int t4 = lane >> 3;             // tile index 0..3
    const int rs = lane & 7;              // row within tile

    for (int t = 0; t < KT; t++) {
        if (t < KT - 1) asm volatile("cp.async.wait_group 1;");
        else            asm volatile("cp.async.wait_group 0;");
        __syncthreads();

        if (t + 2 < KT) load_stage((t + 2) % NSTAGES, t + 2);

        const uint32_t sa  = sb + (t % NSTAGES) * STAGE_BYTES;
        const uint32_t sbs = sa + STAGE_A;

        #pragma unroll
        for (int kk = 0; kk < 4; kk++) {
            uint32_t a[2][4], b[8][2];
            // A tiles: t4 -> row_off = (t4&1)*8, chunk = 2kk + (t4>>1)
            #pragma unroll
            for (int mi = 0; mi < 2; mi++) {
                int row = wm + mi * 16 + ((t4 & 1) << 3) + rs;
                int ch  = 2 * kk + (t4 >> 1);
                ldsm4(a[mi][0], a[mi][1], a[mi][2], a[mi][3],
                      sa + row * 128 + (((ch ^ (row & 7))) << 4));
            }
            // B tiles: t4 -> n_off = (t4>>1)*8, chunk = 2kk + (t4&1)
            #pragma unroll
            for (int nb = 0; nb < 4; nb++) {
                int nrow = wn + nb * 16 + ((t4 >> 1) << 3) + rs;
                int ch   = 2 * kk + (t4 & 1);
                ldsm4(b[2 * nb][0], b[2 * nb][1], b[2 * nb + 1][0], b[2 * nb + 1][1],
                      sbs + nrow * 128 + (((ch ^ (nrow & 7))) << 4));
            }
            #pragma unroll
            for (int mi = 0; mi < 2; mi++)
                #pragma unroll
                for (int ni = 0; ni < 8; ni++)
                    asm volatile(
                        "mma.sync.aligned.m16n8k8.row.col.f32.tf32.tf32.f32 "
                        "{%0,%1,%2,%3}, {%4,%5,%6,%7}, {%8,%9}, {%0,%1,%2,%3};"
                        : "+f"(c[mi][ni][0]), "+f"(c[mi][ni][1]),
                          "+f"(c[mi][ni][2]), "+f"(c[mi][ni][3])
                        : "r"(a[mi][0]), "r"(a[mi][1]), "r"(a[mi][2]), "r"(a[mi][3]),
                          "r"(b[ni][0]), "r"(b[ni][1]));
        }
        __syncthreads();
    }

    // epilogue: bias add + fp32 store
    #pragma unroll
    for (int mi = 0; mi < 2; mi++) {
        const int row = bm + wm + mi * 16 + (lane >> 2);
        #pragma unroll
        for (int ni = 0; ni < 8; ni++) {
            const int col = bn + wn + ni * 8 + 2 * (lane & 3);
            const float2 bv = *reinterpret_cast<const float2*>(bias + col);
            float2 r0 = make_float2(c[mi][ni][0] + bv.x, c[mi][ni][1] + bv.y);
            float2 r1 = make_float2(c[mi][ni][2] + bv.x, c[mi][ni][3] + bv.y);
            *reinterpret_cast<float2*>(out + (size_t)row * N_DIM + col) = r0;
            *reinterpret_cast<float2*>(out + (size_t)(row + 8) * N_DIM + col) = r1;
        }
    }
}

// ---------------------------------------------------------------------------
extern "C" void kernel_launch(void* const* d_in, const int* in_sizes, int n_in,
                              void* d_out, int out_size) {
    const float* x         = (const float*)d_in[0];
    const float* centroids = (const float*)d_in[1];
    const void*  labels    = d_in[2];
    const float* scale     = (const float*)d_in[3];
    const float* bias      = (const float*)d_in[4];
    float* out = (float*)d_out;

    const int M = in_sizes[0] / K_DIM;   // 8192

    detect_labels_kernel<<<1, 32>>>((const int*)labels);
    dequant_kernel<<<dim3(K_DIM / 64, N_DIM / 128), 256>>>(centroids, labels, scale);
    const int n4 = (M * K_DIM) / 4;
    round_x_kernel<<<(n4 + 255) / 256, 256>>>(x, n4);

    const size_t smem = (size_t)NSTAGES * STAGE_BYTES;   // 98304 B
    cudaFuncSetAttribute(gemm_kernel, cudaFuncAttributeMaxDynamicSharedMemorySize, (int)smem);
    gemm_kernel<<<dim3(N_DIM / BN, M / BM), NTHREADS, smem>>>(bias, out);
}

// round 6
// speedup vs baseline: 2.5065x; 1.8817x over previous
#include <cuda_runtime.h>
#include <cuda_fp16.h>
#include <cstdint>

#define K_DIM 4096
#define N_DIM 4096
#define NG    512
#define M_MAX 8192

// ---- GEMM tiling (fp16 operands) ----
#define BM 128
#define BN 128
#define BKH 64                  // halves per k-stage = 128 B per row (SW128 domain)
#define NSTAGES 3
#define NTHREADS 256
#define STAGE_A 16384           // 128 rows x 128 B
#define STAGE_B 16384
#define STAGE_BYTES (STAGE_A + STAGE_B)

#define HCLAMP 65472.0f

// Scratch (static __device__: allowed)
__device__ __half g_X[(size_t)M_MAX * K_DIM];   // x * alpha_k, fp16      [M,K]
__device__ __half g_B[(size_t)N_DIM * K_DIM];   // W / alpha_k, fp16, K-major [N,K]
__device__ float  g_alpha[K_DIM];               // per-k power-of-2 rebalance
__device__ int    g_lab64;

// ---------------- helpers ----------------
__device__ __forceinline__ uint32_t smem_u32(const void* p) {
    uint32_t a;
    asm("{ .reg .u64 t; cvta.to.shared.u64 t, %1; cvt.u32.u64 %0, t; }" : "=r"(a) : "l"(p));
    return a;
}
__device__ __forceinline__ void cp16(uint32_t saddr, const void* g) {
    asm volatile("cp.async.cg.shared.global [%0], [%1], 16;" :: "r"(saddr), "l"(g));
}
__device__ __forceinline__ void ldsm4(uint32_t& r0, uint32_t& r1, uint32_t& r2, uint32_t& r3,
                                      uint32_t addr) {
    asm volatile("ldmatrix.sync.aligned.m8n8.x4.shared.b16 {%0,%1,%2,%3}, [%4];"
                 : "=r"(r0), "=r"(r1), "=r"(r2), "=r"(r3) : "r"(addr));
}
__device__ __forceinline__ float hclamp(float v) {
    return fminf(fmaxf(v, -HCLAMP), HCLAMP);
}
__device__ __forceinline__ uint32_t h2_bits(__half2 h) {
    uint32_t u;
    memcpy(&u, &h, 4);
    return u;
}

// ---------------------------------------------------------------------------
// label dtype detection (jax may deliver int32 or int64)
// ---------------------------------------------------------------------------
__global__ void detect_labels_kernel(const int* __restrict__ labels32) {
    if (threadIdx.x == 0) {
        int all_zero = 1;
        for (int i = 0; i < 64; i++)
            if (labels32[2 * i + 1] != 0) { all_zero = 0; break; }
        g_lab64 = all_zero;
    }
}

// ---------------------------------------------------------------------------
// per-k rebalance factor: alpha_k = 2^e, e = clamp(ceil(-log2(s)/2), 0, 12)
// ---------------------------------------------------------------------------
__global__ void alpha_kernel(const float* __restrict__ scale) {
    int k = blockIdx.x * blockDim.x + threadIdx.x;
    if (k >= K_DIM) return;
    float s = fmaxf(scale[k], 1e-8f);
    int e = (int)ceilf(-0.5f * log2f(s));
    e = max(0, min(12, e));
    g_alpha[k] = (float)(1u << e);
}

// ---------------------------------------------------------------------------
// dequant + transpose: g_B[n][k] = fp16( centroids[labels[k,n/8]][n%8] /
//                                        (max(scale[k],1e-8) * alpha_k) )
// ---------------------------------------------------------------------------
__global__ void __launch_bounds__(256) dequant_kernel(const float* __restrict__ centroids,
                                                      const void* __restrict__ labels_raw,
                                                      const float* __restrict__ scale) {
    __shared__ float tile[128][65];
    const int tid = threadIdx.x;
    const int k0 = blockIdx.x * 64;
    const int n0 = blockIdx.y * 128;
    const int g0 = n0 >> 3;
    const bool l64 = (g_lab64 != 0);

    #pragma unroll
    for (int it = 0; it < 4; it++) {
        int id = it * 256 + tid;          // 1024 items: 64 k x 16 groups
        int kl = id >> 4, g = id & 15;
        int k = k0 + kl;
        long long lab = l64 ? ((const long long*)labels_raw)[(size_t)k * NG + g0 + g]
                            : (long long)((const int*)labels_raw)[(size_t)k * NG + g0 + g];
        float rs = 1.0f / (fmaxf(__ldg(scale + k), 1e-8f) * g_alpha[k]);
        const float4* c = reinterpret_cast<const float4*>(centroids + (size_t)lab * 8);
        float4 v0 = __ldg(c), v1 = __ldg(c + 1);
        int nb = g * 8;
        tile[nb + 0][kl] = v0.x * rs; tile[nb + 1][kl] = v0.y * rs;
        tile[nb + 2][kl] = v0.z * rs; tile[nb + 3][kl] = v0.w * rs;
        tile[nb + 4][kl] = v1.x * rs; tile[nb + 5][kl] = v1.y * rs;
        tile[nb + 6][kl] = v1.z * rs; tile[nb + 7][kl] = v1.w * rs;
    }
    __syncthreads();
    #pragma unroll
    for (int it = 0; it < 8; it++) {
        int id = it * 256 + tid;          // 2048 items: 128 n x 16 k-quads
        int nl = id >> 4, k4 = (id & 15) * 4;
        __half2 h0 = __floats2half2_rn(hclamp(tile[nl][k4]),     hclamp(tile[nl][k4 + 1]));
        __half2 h1 = __floats2half2_rn(hclamp(tile[nl][k4 + 2]), hclamp(tile[nl][k4 + 3]));
        uint2 v = make_uint2(h2_bits(h0), h2_bits(h1));
        *reinterpret_cast<uint2*>(g_B + (size_t)(n0 + nl) * K_DIM + k0 + k4) = v;
    }
}

// ---------------------------------------------------------------------------
// x' = fp16(x * alpha_k): 8 halves per thread
// ---------------------------------------------------------------------------
__global__ void round_x_kernel(const float* __restrict__ x, int n8) {
    int idx = blockIdx.x * blockDim.x + threadIdx.x;
    if (idx >= n8) return;
    const int kb = (idx * 8) & (K_DIM - 1);
    float4 a = __ldg(reinterpret_cast<const float4*>(x) + idx * 2);
    float4 b = __ldg(reinterpret_cast<const float4*>(x) + idx * 2 + 1);
    float4 al0 = *reinterpret_cast<const float4*>(g_alpha + kb);
    float4 al1 = *reinterpret_cast<const float4*>(g_alpha + kb + 4);
    __half2 h0 = __floats2half2_rn(hclamp(a.x * al0.x), hclamp(a.y * al0.y));
    __half2 h1 = __floats2half2_rn(hclamp(a.z * al0.z), hclamp(a.w * al0.w));
    __half2 h2 = __floats2half2_rn(hclamp(b.x * al1.x), hclamp(b.y * al1.y));
    __half2 h3 = __floats2half2_rn(hclamp(b.z * al1.z), hclamp(b.w * al1.w));
    uint4 v = make_uint4(h2_bits(h0), h2_bits(h1), h2_bits(h2), h2_bits(h3));
    reinterpret_cast<uint4*>(g_X)[idx] = v;
}

// ---------------------------------------------------------------------------
// GEMM: out = g_X @ g_B^T + bias.  128x128 CTA tile, 8 warps of 32x64,
// BK=64 halves, 3-stage cp.async, SW128 swizzled smem, ldmatrix,
// m16n8k16 fp16 mma.sync with fp32 accumulate.
// ---------------------------------------------------------------------------
__global__ void __launch_bounds__(NTHREADS, 2)
gemm_kernel(const float* __restrict__ bias, float* __restrict__ out) {
    extern __shared__ char smem_raw[];
    const uint32_t sb = smem_u32(smem_raw);

    const int tid  = threadIdx.x;
    const int wid  = tid >> 5;
    const int lane = tid & 31;
    const int bm = blockIdx.y * BM;
    const int bn = blockIdx.x * BN;
    const int wm = (wid & 3) * 32;        // warp tile 32 (m) x 64 (n)
    const int wn = (wid >> 2) * 64;

    float c[2][8][4];
    #pragma unroll
    for (int mi = 0; mi < 2; mi++)
        #pragma unroll
        for (int ni = 0; ni < 8; ni++) {
            c[mi][ni][0] = 0.f; c[mi][ni][1] = 0.f;
            c[mi][ni][2] = 0.f; c[mi][ni][3] = 0.f;
        }

    const int KT = K_DIM / BKH;           // 64

    const __half* gA0 = g_X + (size_t)bm * K_DIM;
    const __half* gB0 = g_B + (size_t)bn * K_DIM;

    auto load_stage = [&](int slot, int t) {
        const uint32_t sa  = sb + slot * STAGE_BYTES;
        const uint32_t sbs = sa + STAGE_A;
        const __half* gA = gA0 + t * BKH;
        const __half* gB = gB0 + t * BKH;
        #pragma unroll
        for (int i = 0; i < 4; i++) {
            int id = i * 256 + tid;
            int r = id >> 3, cc = id & 7;
            cp16(sa + r * 128 + ((cc ^ (r & 7)) << 4), gA + (size_t)r * K_DIM + cc * 8);
        }
        #pragma unroll
        for (int i = 0; i < 4; i++) {
            int id = i * 256 + tid;
            int r = id >> 3, cc = id & 7;
            cp16(sbs + r * 128 + ((cc ^ (r & 7)) << 4), gB + (size_t)r * K_DIM + cc * 8);
        }
        asm volatile("cp.async.commit_group;");
    };

    load_stage(0, 0);
    load_stage(1, 1);

    const int t4 = lane >> 3;             // ldmatrix tile index 0..3
    const int rs = lane & 7;              // row within 8x8 tile

    for (int t = 0; t < KT; t++) {
        if (t < KT - 1) asm volatile("cp.async.wait_group 1;");
        else            asm volatile("cp.async.wait_group 0;");
        __syncthreads();

        if (t + 2 < KT) load_stage((t + 2) % NSTAGES, t + 2);

        const uint32_t sa  = sb + (t % NSTAGES) * STAGE_BYTES;
        const uint32_t sbs = sa + STAGE_A;

        #pragma unroll
        for (int kk = 0; kk < 4; kk++) {      // 4 x k16 chunks
            uint32_t a[2][4], b[8][2];
            // A: matrix0..3 = (rows +0/+8) x (k16 lower/upper 8-half chunk)
            #pragma unroll
            for (int mi = 0; mi < 2; mi++) {
                int row = wm + mi * 16 + ((t4 & 1) << 3) + rs;
                int ch  = 2 * kk + (t4 >> 1);
                ldsm4(a[mi][0], a[mi][1], a[mi][2], a[mi][3],
                      sa + row * 128 + ((ch ^ (row & 7)) << 4));
            }
            // B: matrix0..3 = (n +0/+8) x (k16 lower/upper chunk)
            #pragma unroll
            for (int nb = 0; nb < 4; nb++) {
                int nrow = wn + nb * 16 + ((t4 >> 1) << 3) + rs;
                int ch   = 2 * kk + (t4 & 1);
                ldsm4(b[2 * nb][0], b[2 * nb][1], b[2 * nb + 1][0], b[2 * nb + 1][1],
                      sbs + nrow * 128 + ((ch ^ (nrow & 7)) << 4));
            }
            #pragma unroll
            for (int mi = 0; mi < 2; mi++)
                #pragma unroll
                for (int ni = 0; ni < 8; ni++)
                    asm volatile(
                        "mma.sync.aligned.m16n8k16.row.col.f32.f16.f16.f32 "
                        "{%0,%1,%2,%3}, {%4,%5,%6,%7}, {%8,%9}, {%0,%1,%2,%3};"
                        : "+f"(c[mi][ni][0]), "+f"(c[mi][ni][1]),
                          "+f"(c[mi][ni][2]), "+f"(c[mi][ni][3])
                        : "r"(a[mi][0]), "r"(a[mi][1]), "r"(a[mi][2]), "r"(a[mi][3]),
                          "r"(b[ni][0]), "r"(b[ni][1]));
        }
        __syncthreads();
    }

    // epilogue: bias add + fp32 store
    #pragma unroll
    for (int mi = 0; mi < 2; mi++) {
        const int row = bm + wm + mi * 16 + (lane >> 2);
        #pragma unroll
        for (int ni = 0; ni < 8; ni++) {
            const int col = bn + wn + ni * 8 + 2 * (lane & 3);
            const float2 bv = *reinterpret_cast<const float2*>(bias + col);
            float2 r0 = make_float2(c[mi][ni][0] + bv.x, c[mi][ni][1] + bv.y);
            float2 r1 = make_float2(c[mi][ni][2] + bv.x, c[mi][ni][3] + bv.y);
            *reinterpret_cast<float2*>(out + (size_t)row * N_DIM + col) = r0;
            *reinterpret_cast<float2*>(out + (size_t)(row + 8) * N_DIM + col) = r1;
        }
    }
}

// ---------------------------------------------------------------------------
extern "C" void kernel_launch(void* const* d_in, const int* in_sizes, int n_in,
                              void* d_out, int out_size) {
    const float* x         = (const float*)d_in[0];
    const float* centroids = (const float*)d_in[1];
    const void*  labels    = d_in[2];
    const float* scale     = (const float*)d_in[3];
    const float* bias      = (const float*)d_in[4];
    float* out = (float*)d_out;

    const int M = in_sizes[0] / K_DIM;   // 8192

    detect_labels_kernel<<<1, 32>>>((const int*)labels);
    alpha_kernel<<<K_DIM / 256, 256>>>(scale);
    dequant_kernel<<<dim3(K_DIM / 64, N_DIM / 128), 256>>>(centroids, labels, scale);
    const int n8 = (M * K_DIM) / 8;
    round_x_kernel<<<(n8 + 255) / 256, 256>>>(x, n8);

    const size_t smem = (size_t)NSTAGES * STAGE_BYTES;   // 98304 B
    cudaFuncSetAttribute(gemm_kernel, cudaFuncAttributeMaxDynamicSharedMemorySize, (int)smem);
    gemm_kernel<<<dim3(N_DIM / BN, M / BM), NTHREADS, smem>>>(bias, out);
}